// round 2
// baseline (speedup 1.0000x reference)
#include <cuda_runtime.h>
#include <math.h>

#define NN 100000
#define DD 128
#define OO 128
#define VV 3
#define EE 400000
#define HH 64
#define RS 129
#define NBLK 782
#define WBF 16448
#define SMEM_BYTES ((2 * 128 * RS + WBF) * 4)

// ---------------- device scratch (no runtime alloc allowed) ----------------
__device__ float g_X[VV * NN * DD];      // scattered weighted features
__device__ float g_s[VV * NN];           // per-node edge-weight sums
__device__ float g_att[NN];              // node attention
__device__ float g_sfus[NN * OO];        // self_out @ fus_w_top
__device__ float g_trans[NN * OO];       // features @ ft_w + ft_b
__device__ float g_views[VV * NN * OO];  // per-view outputs
__device__ float g_vscore[VV * NN];      // view attention logits

// ---------------- packed f32x2 helpers ----------------
__device__ __forceinline__ unsigned long long pack2(float x, float y) {
    unsigned long long r;
    asm("mov.b64 %0, {%1,%2};" : "=l"(r) : "f"(x), "f"(y));
    return r;
}
__device__ __forceinline__ float2 unpack2(unsigned long long v) {
    float2 f;
    asm("mov.b64 {%0,%1}, %2;" : "=f"(f.x), "=f"(f.y) : "l"(v));
    return f;
}
__device__ __forceinline__ unsigned long long fma2(unsigned long long a,
                                                   unsigned long long b,
                                                   unsigned long long c) {
    unsigned long long d;
    asm("fma.rn.f32x2 %0, %1, %2, %3;" : "=l"(d) : "l"(a), "l"(b), "l"(c));
    return d;
}
__device__ __forceinline__ float sigm(float x) { return 1.0f / (1.0f + expf(-x)); }

// ---------------- smem loaders ----------------
__device__ __forceinline__ void load_tile(float* dst, const float* __restrict__ src,
                                          int nb, int t) {
    for (int idx = t; idx < 128 * 32; idx += 256) {
        int r = idx >> 5, cv = idx & 31;
        float4 val = make_float4(0.f, 0.f, 0.f, 0.f);
        if (nb + r < NN) val = ((const float4*)src)[(size_t)(nb + r) * 32 + cv];
        float* d = dst + r * RS + cv * 4;
        d[0] = val.x; d[1] = val.y; d[2] = val.z; d[3] = val.w;
    }
}
__device__ __forceinline__ void load_w(float* wb, const float* __restrict__ src,
                                       int cnt, int t) {
    const float4* s = (const float4*)src;
    float4* d = (float4*)wb;
    for (int i = t; i < (cnt >> 2); i += 256) d[i] = s[i];
}

// ---------------- core: 128-k matmul, NCH 4-wide output chunks ----------------
template <int NCH, int WS, int CS>
__device__ __forceinline__ void mm_core(const float* __restrict__ srow,
                                        const float* __restrict__ wbase,
                                        unsigned long long* acc) {
#pragma unroll 4
    for (int k = 0; k < 128; k++) {
        float a = srow[k];
        unsigned long long aa = pack2(a, a);
        const float* wr = wbase + k * WS;
#pragma unroll
        for (int jc = 0; jc < NCH; jc++) {
            ulonglong2 w2 = *(const ulonglong2*)(wr + CS * jc);
            acc[2 * jc]     = fma2(w2.x, aa, acc[2 * jc]);
            acc[2 * jc + 1] = fma2(w2.y, aa, acc[2 * jc + 1]);
        }
    }
}

// =====================================================================
__global__ void k_zero() {
    size_t tid = (size_t)blockIdx.x * blockDim.x + threadIdx.x;
    size_t stride = (size_t)gridDim.x * blockDim.x;
    float4 z = make_float4(0.f, 0.f, 0.f, 0.f);
    float4* X = (float4*)g_X;
    size_t nx = (size_t)VV * NN * DD / 4;
    for (size_t i = tid; i < nx; i += stride) X[i] = z;
    float4* S = (float4*)g_s;
    for (size_t i = tid; i < VV * NN / 4; i += stride) S[i] = z;
}

// =====================================================================
// K1: class_probs, node_att, g_sfus = self@fus_top, g_trans = f@ft_w+b
// =====================================================================
__global__ void __launch_bounds__(256, 1) k_node(
    const float* __restrict__ feat,
    const float* __restrict__ la_w1, const float* __restrict__ la_b1,
    const float* __restrict__ la_w2, const float* __restrict__ la_b2,
    const float* __restrict__ pred_w, const float* __restrict__ pred_b,
    const float* __restrict__ att_bias,
    const float* __restrict__ sl_w, const float* __restrict__ sl_b,
    const float* __restrict__ fus_w,
    const float* __restrict__ ft_w, const float* __restrict__ ft_b,
    float* __restrict__ probs, int write_probs) {
    extern __shared__ float sm[];
    float* sf = sm;
    float* ss = sm + 128 * RS;
    float* wb = sm + 2 * 128 * RS;
    const int t = threadIdx.x;
    const int nb = blockIdx.x * 128;
    const int i = t >> 1, half = t & 1;
    const int n = nb + i;
    const bool valid = n < NN;
    const float* srow = sf + i * RS;
    const int jo = 4 * half;

    load_tile(sf, feat, nb, t);
    load_w(wb, la_w1, DD * HH, t);
    load_w(wb + DD * HH + 4, la_w1 + DD * HH, DD * HH, t);  // +4 skew
    __syncthreads();

    // ---- label-aware attention (this thread's class = half) ----
    {
        const int c = half;
        float lg = pred_b[c];
#pragma unroll 8
        for (int k = 0; k < 128; k++) lg += srow[k] * __ldg(&pred_w[k * 2 + c]);

        unsigned long long acc[32];
        const float* b1 = la_b1 + c * HH;
#pragma unroll
        for (int jc = 0; jc < 16; jc++) {
            acc[2 * jc]     = pack2(b1[4 * jc], b1[4 * jc + 1]);
            acc[2 * jc + 1] = pack2(b1[4 * jc + 2], b1[4 * jc + 3]);
        }
        mm_core<16, HH, 4>(srow, wb + c * (DD * HH + 4), acc);
        float dot = la_b2[c];
        const float* w2 = la_w2 + c * HH;
#pragma unroll
        for (int jc = 0; jc < 16; jc++) {
            float2 lo = unpack2(acc[2 * jc]), hi = unpack2(acc[2 * jc + 1]);
            dot += fmaxf(lo.x, 0.f) * w2[4 * jc] + fmaxf(lo.y, 0.f) * w2[4 * jc + 1] +
                   fmaxf(hi.x, 0.f) * w2[4 * jc + 2] + fmaxf(hi.y, 0.f) * w2[4 * jc + 3];
        }
        float score = sigm(dot);
        float lg_o = __shfl_xor_sync(0xffffffffu, lg, 1);
        float mx = fmaxf(lg, lg_o);
        float e = expf(lg - mx), e_o = expf(lg_o - mx);
        float p = e / (e + e_o);
        float ap = score * p;
        float att = ap + __shfl_xor_sync(0xffffffffu, ap, 1) + att_bias[0];
        if (valid) {
            if (write_probs) probs[(size_t)n * 2 + c] = p;
            if (c == 0) g_att[n] = att;
        }
    }
    __syncthreads();

    // ---- self = f@sl_w + sl_b -> ss ----
    load_w(wb, sl_w, DD * OO, t);
    __syncthreads();
    {
        unsigned long long acc[32];
        const float* b = sl_b + jo;
#pragma unroll
        for (int jc = 0; jc < 16; jc++) {
            float4 b4 = *(const float4*)(b + 8 * jc);
            acc[2 * jc]     = pack2(b4.x, b4.y);
            acc[2 * jc + 1] = pack2(b4.z, b4.w);
        }
        mm_core<16, OO, 8>(srow, wb + jo, acc);
        float* sr = ss + i * RS + jo;
#pragma unroll
        for (int jc = 0; jc < 16; jc++) {
            float2 lo = unpack2(acc[2 * jc]), hi = unpack2(acc[2 * jc + 1]);
            sr[8 * jc] = lo.x; sr[8 * jc + 1] = lo.y;
            sr[8 * jc + 2] = hi.x; sr[8 * jc + 3] = hi.y;
        }
    }
    __syncthreads();

    // ---- sfus = self @ fus_w[0:128] (bias deferred) ----
    load_w(wb, fus_w, DD * OO, t);
    __syncthreads();
    {
        unsigned long long acc[32];
#pragma unroll
        for (int jc = 0; jc < 32; jc++) acc[jc] = 0ull;
        mm_core<16, OO, 8>(ss + i * RS, wb + jo, acc);
        if (valid) {
            float* dst = g_sfus + (size_t)n * OO + jo;
#pragma unroll
            for (int jc = 0; jc < 16; jc++) {
                float2 lo = unpack2(acc[2 * jc]), hi = unpack2(acc[2 * jc + 1]);
                *(float4*)(dst + 8 * jc) = make_float4(lo.x, lo.y, hi.x, hi.y);
            }
        }
    }
    __syncthreads();

    // ---- trans = f@ft_w + ft_b ----
    load_w(wb, ft_w, DD * OO, t);
    __syncthreads();
    {
        unsigned long long acc[32];
        const float* b = ft_b + jo;
#pragma unroll
        for (int jc = 0; jc < 16; jc++) {
            float4 b4 = *(const float4*)(b + 8 * jc);
            acc[2 * jc]     = pack2(b4.x, b4.y);
            acc[2 * jc + 1] = pack2(b4.z, b4.w);
        }
        mm_core<16, OO, 8>(srow, wb + jo, acc);
        if (valid) {
            float* dst = g_trans + (size_t)n * OO + jo;
#pragma unroll
            for (int jc = 0; jc < 16; jc++) {
                float2 lo = unpack2(acc[2 * jc]), hi = unpack2(acc[2 * jc + 1]);
                *(float4*)(dst + 8 * jc) = make_float4(lo.x, lo.y, hi.x, hi.y);
            }
        }
    }
}

// =====================================================================
// K2: edge scatter — g_X[v][dst] += w_e * f[src], g_s[v][dst] += w_e
// =====================================================================
__global__ void __launch_bounds__(256) k_scatter(const float* __restrict__ feat,
                                                 const int* __restrict__ ei,
                                                 const float* __restrict__ ew) {
    int gw = blockIdx.x * 8 + (threadIdx.x >> 5);
    int lane = threadIdx.x & 31;
    int v = gw / EE;
    int e = gw - v * EE;
    int src = ei[(size_t)v * 2 * EE + e];
    int dst = ei[(size_t)v * 2 * EE + EE + e];
    float w = ew[(size_t)v * EE + e];
    float4 m = ((const float4*)feat)[(size_t)src * 32 + lane];
    float* X = g_X + ((size_t)v * NN + dst) * DD + lane * 4;
    atomicAdd(X + 0, m.x * w);
    atomicAdd(X + 1, m.y * w);
    atomicAdd(X + 2, m.z * w);
    atomicAdd(X + 3, m.w * w);
    if (lane == 0) atomicAdd(&g_s[(size_t)v * NN + dst], w);
}

// =====================================================================
// K3: per-view agg -> gate -> view -> pe -> view-attention logits
// =====================================================================
__global__ void __launch_bounds__(256, 1) k_view(
    const float* __restrict__ rel_w, const float* __restrict__ rel_b,
    const float* __restrict__ gate_w, const float* __restrict__ gate_b,
    const float* __restrict__ view_pref,
    const float* __restrict__ va_w1, const float* __restrict__ va_b1,
    const float* __restrict__ va_w2, const float* __restrict__ va_b2) {
    extern __shared__ float sm[];
    float* sx = sm;                 // X tile, later pe tile
    float* sa = sm + 128 * RS;      // agg tile
    float* wb = sm + 2 * 128 * RS;
    const int t = threadIdx.x;
    const int v = blockIdx.y;
    const int nb = blockIdx.x * 128;
    const int i = t >> 1, half = t & 1;
    const int n = nb + i;
    const bool valid = n < NN;
    const int nc = valid ? n : 0;
    const int jo = 4 * half;
    const float* srow = sx + i * RS;
    float* arow = sa + i * RS;

    load_tile(sx, g_X + (size_t)v * NN * DD, nb, t);
    load_w(wb, rel_w + (size_t)v * DD * OO, DD * OO, t);
    __syncthreads();

    const float sn = g_s[(size_t)v * NN + nc];

    // ---- agg = X@rel_w + rel_b*s ----
    {
        unsigned long long acc[32];
        const float* rb = rel_b + v * OO + jo;
#pragma unroll
        for (int jc = 0; jc < 16; jc++) {
            float4 b4 = *(const float4*)(rb + 8 * jc);
            acc[2 * jc]     = pack2(b4.x * sn, b4.y * sn);
            acc[2 * jc + 1] = pack2(b4.z * sn, b4.w * sn);
        }
        mm_core<16, OO, 8>(srow, wb + jo, acc);
        float* ar = arow + jo;
#pragma unroll
        for (int jc = 0; jc < 16; jc++) {
            float2 lo = unpack2(acc[2 * jc]), hi = unpack2(acc[2 * jc + 1]);
            ar[8 * jc] = lo.x; ar[8 * jc + 1] = lo.y;
            ar[8 * jc + 2] = hi.x; ar[8 * jc + 3] = hi.y;
        }
    }
    __syncthreads();
    load_w(wb, gate_w + (size_t)v * OO * OO, OO * OO, t);
    __syncthreads();

    // ---- gate = sigmoid(agg@gate_w+gate_b); view = gate*agg; pe = view*pref ----
    {
        unsigned long long acc[32];
        const float* gb = gate_b + v * OO + jo;
#pragma unroll
        for (int jc = 0; jc < 16; jc++) {
            float4 b4 = *(const float4*)(gb + 8 * jc);
            acc[2 * jc]     = pack2(b4.x, b4.y);
            acc[2 * jc + 1] = pack2(b4.z, b4.w);
        }
        mm_core<16, OO, 8>(arow, wb + jo, acc);
        float* vr = sx + i * RS + jo;  // overwrite X tile with pe
        float* gv = g_views + ((size_t)v * NN + nc) * OO + jo;
        const float* vp = view_pref + v * OO + jo;
        const float* ar = arow + jo;
#pragma unroll
        for (int jc = 0; jc < 16; jc++) {
            float2 lo = unpack2(acc[2 * jc]), hi = unpack2(acc[2 * jc + 1]);
            float v0 = sigm(lo.x) * ar[8 * jc];
            float v1 = sigm(lo.y) * ar[8 * jc + 1];
            float v2 = sigm(hi.x) * ar[8 * jc + 2];
            float v3 = sigm(hi.y) * ar[8 * jc + 3];
            if (valid) *(float4*)(gv + 8 * jc) = make_float4(v0, v1, v2, v3);
            float4 p4 = *(const float4*)(vp + 8 * jc);
            vr[8 * jc] = v0 * p4.x; vr[8 * jc + 1] = v1 * p4.y;
            vr[8 * jc + 2] = v2 * p4.z; vr[8 * jc + 3] = v3 * p4.w;
        }
    }
    __syncthreads();
    load_w(wb, va_w1, OO * HH, t);
    __syncthreads();

    // ---- vh = relu(pe@va_w1+va_b1); vscore = vh.va_w2 + va_b2 ----
    {
        unsigned long long acc[16];
        const float* b1 = va_b1 + jo;
#pragma unroll
        for (int jc = 0; jc < 8; jc++) {
            float4 b4 = *(const float4*)(b1 + 8 * jc);
            acc[2 * jc]     = pack2(b4.x, b4.y);
            acc[2 * jc + 1] = pack2(b4.z, b4.w);
        }
        mm_core<8, HH, 8>(srow, wb + jo, acc);
        float dot = 0.f;
        const float* w2 = va_w2 + jo;
#pragma unroll
        for (int jc = 0; jc < 8; jc++) {
            float2 lo = unpack2(acc[2 * jc]), hi = unpack2(acc[2 * jc + 1]);
            float4 w4 = *(const float4*)(w2 + 8 * jc);
            dot += fmaxf(lo.x, 0.f) * w4.x + fmaxf(lo.y, 0.f) * w4.y +
                   fmaxf(hi.x, 0.f) * w4.z + fmaxf(hi.y, 0.f) * w4.w;
        }
        dot += __shfl_xor_sync(0xffffffffu, dot, 1);
        if (valid && half == 0) g_vscore[(size_t)v * NN + n] = dot + va_b2[0];
    }
}

// =====================================================================
// K4: view softmax, combine, fuse, layernorm -> out
// =====================================================================
__global__ void __launch_bounds__(256, 1) k_final(
    const float* __restrict__ fus_w_bot, const float* __restrict__ fus_b,
    const float* __restrict__ ln_g, const float* __restrict__ ln_beta,
    float* __restrict__ out) {
    extern __shared__ float sm[];
    float* sx = sm;
    float* wb = sm + 2 * 128 * RS;
    const int t = threadIdx.x;
    const int nb = blockIdx.x * 128;
    const int i = t >> 1, half = t & 1;
    const int n = nb + i;
    const bool valid = n < NN;
    const int nc = valid ? n : 0;
    const int jo = 4 * half;

    load_w(wb, fus_w_bot, DD * OO, t);

    float s0 = g_vscore[0 * NN + nc], s1 = g_vscore[1 * NN + nc], s2 = g_vscore[2 * NN + nc];
    float m = fmaxf(s0, fmaxf(s1, s2));
    float e0 = expf(s0 - m), e1 = expf(s1 - m), e2 = expf(s2 - m);
    float inv = 1.f / (e0 + e1 + e2);
    float p0 = e0 * inv, p1 = e1 * inv, p2 = e2 * inv;
    float att = g_att[nc];

    float* wr = sx + i * RS + jo;
    const float* v0p = g_views + (size_t)(0 * NN + nc) * OO + jo;
    const float* v1p = g_views + ((size_t)1 * NN + nc) * OO + jo;
    const float* v2p = g_views + ((size_t)2 * NN + nc) * OO + jo;
#pragma unroll
    for (int jc = 0; jc < 16; jc++) {
        float4 a = *(const float4*)(v0p + 8 * jc);
        float4 b = *(const float4*)(v1p + 8 * jc);
        float4 c = *(const float4*)(v2p + 8 * jc);
        wr[8 * jc]     = att * (a.x * p0 + b.x * p1 + c.x * p2);
        wr[8 * jc + 1] = att * (a.y * p0 + b.y * p1 + c.y * p2);
        wr[8 * jc + 2] = att * (a.z * p0 + b.z * p1 + c.z * p2);
        wr[8 * jc + 3] = att * (a.w * p0 + b.w * p1 + c.w * p2);
    }
    __syncthreads();

    unsigned long long acc[32];
    const float* sf = g_sfus + (size_t)nc * OO + jo;
    const float* fb = fus_b + jo;
#pragma unroll
    for (int jc = 0; jc < 16; jc++) {
        float4 s4 = *(const float4*)(sf + 8 * jc);
        float4 b4 = *(const float4*)(fb + 8 * jc);
        acc[2 * jc]     = pack2(s4.x + b4.x, s4.y + b4.y);
        acc[2 * jc + 1] = pack2(s4.z + b4.z, s4.w + b4.w);
    }
    mm_core<16, OO, 8>(sx + i * RS, wb + jo, acc);

    float o[64];
    float sum = 0.f, sq = 0.f;
    const float* tr = g_trans + (size_t)nc * OO + jo;
#pragma unroll
    for (int jc = 0; jc < 16; jc++) {
        float2 lo = unpack2(acc[2 * jc]), hi = unpack2(acc[2 * jc + 1]);
        float4 t4 = *(const float4*)(tr + 8 * jc);
        float o0 = fmaxf(lo.x, 0.f) + t4.x, o1 = fmaxf(lo.y, 0.f) + t4.y;
        float o2 = fmaxf(hi.x, 0.f) + t4.z, o3 = fmaxf(hi.y, 0.f) + t4.w;
        o[4 * jc] = o0; o[4 * jc + 1] = o1; o[4 * jc + 2] = o2; o[4 * jc + 3] = o3;
        sum += o0 + o1 + o2 + o3;
        sq += o0 * o0 + o1 * o1 + o2 * o2 + o3 * o3;
    }
    sum += __shfl_xor_sync(0xffffffffu, sum, 1);
    sq += __shfl_xor_sync(0xffffffffu, sq, 1);
    float mu = sum * (1.f / 128.f);
    float var = sq * (1.f / 128.f) - mu * mu;
    float rstd = rsqrtf(var + 1e-5f);
    if (valid) {
        float* op = out + (size_t)n * OO + jo;
        const float* gg = ln_g + jo;
        const float* bb = ln_beta + jo;
#pragma unroll
        for (int jc = 0; jc < 16; jc++) {
            float4 g4 = *(const float4*)(gg + 8 * jc);
            float4 b4 = *(const float4*)(bb + 8 * jc);
            float4 r;
            r.x = (o[4 * jc] - mu) * rstd * g4.x + b4.x;
            r.y = (o[4 * jc + 1] - mu) * rstd * g4.y + b4.y;
            r.z = (o[4 * jc + 2] - mu) * rstd * g4.z + b4.z;
            r.w = (o[4 * jc + 3] - mu) * rstd * g4.w + b4.w;
            *(float4*)(op + 8 * jc) = r;
        }
    }
}

// =====================================================================
extern "C" void kernel_launch(void* const* d_in, const int* in_sizes, int n_in,
                              void* d_out, int out_size) {
    const float* feat     = (const float*)d_in[0];
    const int*   ei       = (const int*)d_in[1];
    const float* ew       = (const float*)d_in[2];
    const float* rel_w    = (const float*)d_in[3];
    const float* rel_b    = (const float*)d_in[4];
    const float* gate_w   = (const float*)d_in[5];
    const float* gate_b   = (const float*)d_in[6];
    const float* la_w1    = (const float*)d_in[7];
    const float* la_b1    = (const float*)d_in[8];
    const float* la_w2    = (const float*)d_in[9];
    const float* la_b2    = (const float*)d_in[10];
    const float* pred_w   = (const float*)d_in[11];
    const float* pred_b   = (const float*)d_in[12];
    const float* att_bias = (const float*)d_in[13];
    const float* view_pref= (const float*)d_in[14];
    const float* va_w1    = (const float*)d_in[15];
    const float* va_b1    = (const float*)d_in[16];
    const float* va_w2    = (const float*)d_in[17];
    const float* va_b2    = (const float*)d_in[18];
    const float* ft_w     = (const float*)d_in[19];
    const float* ft_b     = (const float*)d_in[20];
    const float* sl_w     = (const float*)d_in[21];
    const float* sl_b     = (const float*)d_in[22];
    const float* fus_w    = (const float*)d_in[23];
    const float* fus_b    = (const float*)d_in[24];
    const float* ln_g     = (const float*)d_in[25];
    const float* ln_beta  = (const float*)d_in[26];
    float* out = (float*)d_out;

    cudaFuncSetAttribute(k_node, cudaFuncAttributeMaxDynamicSharedMemorySize, SMEM_BYTES);
    cudaFuncSetAttribute(k_view, cudaFuncAttributeMaxDynamicSharedMemorySize, SMEM_BYTES);
    cudaFuncSetAttribute(k_final, cudaFuncAttributeMaxDynamicSharedMemorySize, SMEM_BYTES);

    int write_probs = (out_size >= NN * (OO + 2)) ? 1 : 0;
    float* probs = out + (size_t)NN * OO;

    k_zero<<<2048, 256>>>();
    k_node<<<NBLK, 256, SMEM_BYTES>>>(feat, la_w1, la_b1, la_w2, la_b2,
                                      pred_w, pred_b, att_bias,
                                      sl_w, sl_b, fus_w, ft_w, ft_b,
                                      probs, write_probs);
    k_scatter<<<(VV * EE) / 8, 256>>>(feat, ei, ew);
    k_view<<<dim3(NBLK, VV), 256, SMEM_BYTES>>>(rel_w, rel_b, gate_w, gate_b,
                                                view_pref, va_w1, va_b1, va_w2, va_b2);
    k_final<<<NBLK, 256, SMEM_BYTES>>>(fus_w + DD * OO, fus_b, ln_g, ln_beta, out);
}